// round 1
// baseline (speedup 1.0000x reference)
#include <cuda_runtime.h>

#define H 512
#define W 512
#define TX 32
#define TY 8
#define SW 36   // TX + 4
#define SH 12   // TY + 4

// compare-exchange: a=min, b=max (fp32, no NaNs in input)
#define CE(a, b) { float _lo = fminf(a, b); (b) = fmaxf(a, b); (a) = _lo; }

// Place global min at a[0] and global max at a[N-1], preserving the multiset.
template <int N>
__device__ __forceinline__ void mnmx(float* a) {
    // pairwise: evens hold pair-mins, odds hold pair-maxes
#pragma unroll
    for (int i = 0; i + 1 < N; i += 2) CE(a[i], a[i + 1]);
    // min tree into a[0] (covers all even slots; for odd N this includes a[N-1])
#pragma unroll
    for (int i = 2; i < N; i += 2) CE(a[0], a[i]);
    // max tree into a[N-1] (covers all odd slots; a[N-1] itself stays a candidate)
#pragma unroll
    for (int i = 1; i < N - 1; i += 2) CE(a[i], a[N - 1]);
}

__device__ __forceinline__ int reflect_idx(int i) {
    i = abs(i);                       // -1 -> 1, -2 -> 2
    return (i >= H) ? (2 * H - 2 - i) : i;   // 512 -> 510, 513 -> 509
}

__global__ __launch_bounds__(TX* TY) void median5x5_kernel(
    const float* __restrict__ in, float* __restrict__ out, int planes) {
    __shared__ float tile[SH][SW];

    const int bx = blockIdx.x * TX;
    const int by = blockIdx.y * TY;
    const int plane = blockIdx.z;
    const float* src = in + (size_t)plane * (H * W);

    const int tid = threadIdx.y * TX + threadIdx.x;

    // cooperative halo load with reflect padding
    for (int k = tid; k < SW * SH; k += TX * TY) {
        int sy = k / SW;
        int sx = k - sy * SW;
        int gy = reflect_idx(by + sy - 2);
        int gx = reflect_idx(bx + sx - 2);
        tile[sy][sx] = src[gy * W + gx];
    }
    __syncthreads();

    // this thread's 5x5 window starts at (threadIdx.y, threadIdx.x) in the tile
    const float* p = &tile[threadIdx.y][threadIdx.x];
#define WIN(k) p[((k) / 5) * SW + ((k) % 5)]

    float t[14];
#pragma unroll
    for (int i = 0; i < 14; i++) t[i] = WIN(i);

    // forgetful selection: 6 rounds at s=14 consuming values 14..24
#pragma unroll
    for (int r = 0; r < 5; r++) {
        mnmx<14>(t);
        t[0] = WIN(14 + 2 * r);
        t[13] = WIN(15 + 2 * r);
    }
    mnmx<14>(t);
    // discard t[0], t[13]; bring in last value -> 13 live values in t[0..12]
    t[0] = WIN(24);

    // shrink phase: repeatedly drop min & max from the middle window
    mnmx<13>(t);       // live: t[1..11]  (11 values, median = rank 6)
    mnmx<11>(t + 1);   // live: t[2..10]  (9)
    mnmx<9>(t + 2);    // live: t[3..9]   (7)
    mnmx<7>(t + 3);    // live: t[4..8]   (5)
    mnmx<5>(t + 4);    // live: t[5..7]   (3)

    // median of 3
    float a = t[5], b = t[6], c = t[7];
    float med = fmaxf(fminf(a, b), fminf(fmaxf(a, b), c));

    out[(size_t)plane * (H * W) + (by + threadIdx.y) * W + (bx + threadIdx.x)] = med;
#undef WIN
}

extern "C" void kernel_launch(void* const* d_in, const int* in_sizes, int n_in,
                              void* d_out, int out_size) {
    const float* img = (const float*)d_in[0];
    float* out = (float*)d_out;
    int planes = in_sizes[0] / (H * W);   // 4 * 3 = 12

    dim3 block(TX, TY);
    dim3 grid(W / TX, H / TY, planes);
    median5x5_kernel<<<grid, block>>>(img, out, planes);
}

// round 4
// speedup vs baseline: 1.8696x; 1.8696x over previous
#include <cuda_runtime.h>

#define H 512
#define W 512
#define OW 64
#define OH 8
#define SW (OW + 4)   // 68
#define SH (OH + 4)   // 12
#define NT 256

#define CE(a, b) { float _t = fminf(a, b); (b) = fmaxf(a, b); (a) = _t; }

__device__ __forceinline__ int reflect_idx(int i) {
    i = abs(i);                              // -1 -> 1, -2 -> 2
    return (i >= H) ? (2 * H - 2 - i) : i;   // 512 -> 510, 513 -> 509
}

// optimal 5-sort, 9 CE
__device__ __forceinline__ void sort5(float& x0, float& x1, float& x2, float& x3, float& x4) {
    CE(x0, x1); CE(x3, x4); CE(x2, x4); CE(x2, x3); CE(x0, x3);
    CE(x0, x2); CE(x1, x4); CE(x1, x3); CE(x1, x2);
}

// top-2 of 5, sorted: A <= B (positions 3,4)
__device__ __forceinline__ void top2(float x0, float x1, float x2, float x3, float x4,
                                     float& A, float& B) {
    float a = fminf(x0, x1), b = fmaxf(x0, x1);
    float c = fminf(x2, x3), d = fmaxf(x2, x3);
    float e = fmaxf(a, c);
    float f = fminf(b, d), g = fmaxf(b, d);
    B = fmaxf(g, x4);
    float h = fminf(g, x4);
    A = fmaxf(fmaxf(f, e), h);
}

// top-3 of 5, sorted: C <= D <= E (positions 2,3,4)
__device__ __forceinline__ void top3(float x0, float x1, float x2, float x3, float x4,
                                     float& C, float& D, float& E) {
    float a = fminf(x0, x1), b = fmaxf(x0, x1);
    float c = fminf(x2, x3), d = fmaxf(x2, x3);
    float e = fmaxf(a, c);
    float f = fminf(b, d), g = fmaxf(b, d);
    float p = fminf(e, f), q = fmaxf(e, f);    // top3 of first 4: p<=q<=g
    E = fmaxf(g, x4);
    float u = fminf(g, x4);
    D = fmaxf(q, u);
    float v = fminf(q, u);
    C = fmaxf(p, v);
}

// middle-3 of 5, sorted: F <= G <= Hh (positions 1,2,3)
__device__ __forceinline__ void mid3(float x0, float x1, float x2, float x3, float x4,
                                     float& F, float& G, float& Hh) {
    CE(x0, x1); CE(x2, x3); CE(x0, x2);
    x4 = fmaxf(x0, x4);          // drop global min
    CE(x1, x4);
    x3 = fminf(x3, x4);          // drop global max
    CE(x1, x2); CE(x2, x3); CE(x1, x2);
    F = x1; G = x2; Hh = x3;
}

// bottom-3 of 5, sorted: I <= J <= K (positions 0,1,2)
__device__ __forceinline__ void bot3(float x0, float x1, float x2, float x3, float x4,
                                     float& I, float& J, float& K) {
    float a = fminf(x0, x1), b = fmaxf(x0, x1);
    float c = fminf(x2, x3), d = fmaxf(x2, x3);
    float e = fminf(b, d);
    float f = fminf(a, c), g = fmaxf(a, c);
    float p = fminf(g, e), q = fmaxf(g, e);    // bottom3 of first 4: f<=p<=q
    I = fminf(f, x4);
    float u = fmaxf(f, x4);
    J = fminf(p, u);
    float v = fmaxf(p, u);
    K = fminf(q, v);
}

// bottom-2 of 5, sorted: L <= M (positions 0,1)
__device__ __forceinline__ void bot2(float x0, float x1, float x2, float x3, float x4,
                                     float& L, float& M) {
    float a = fminf(x0, x1), b = fmaxf(x0, x1);
    float c = fminf(x2, x3), d = fmaxf(x2, x3);
    float e = fminf(b, d);
    float f = fminf(a, c), g = fmaxf(a, c);
    L = fminf(f, x4);
    float h = fmaxf(f, x4);
    M = fminf(fminf(g, e), h);
}

// median (7th smallest) of the 13 staircase candidates.
// Chains: A<=B<=E, C<=D<=Hh, F<=G<=K, I<=J<=M, singleton L.
__device__ __forceinline__ float sel13(float A, float B, float C, float D, float E,
                                       float F, float G, float Hh, float I, float J,
                                       float K, float L, float M) {
    // Batcher merge(3,3): P = (A,B,C,D,E,Hh) sorted
    CE(A, C); CE(E, Hh); CE(C, E); CE(B, D); CE(B, C); CE(D, E);
    // Batcher merge(3,3): Q = (F,G,I,J,K,M) sorted
    CE(F, I); CE(K, M); CE(I, K); CE(G, J); CE(G, I); CE(J, K);
    // ranks 5,6 (0-indexed) of P ∪ Q: rank_k = max_{i+j=k} min(P_i, Q_j)
    float s5 = fmaxf(fmaxf(fmaxf(fminf(A, M), fminf(B, K)),
                           fmaxf(fminf(C, J), fminf(D, I))),
                     fmaxf(fminf(E, G), fminf(Hh, F)));
    float s6 = fmaxf(fmaxf(fmaxf(A, fminf(B, M)),
                           fmaxf(fminf(C, K), fminf(D, J))),
                     fmaxf(fmaxf(fminf(E, I), fminf(Hh, G)), F));
    // fold singleton: median of 13 = med3(s5, L, s6), s5 <= s6
    return fminf(fmaxf(s5, L), s6);
}

__global__ __launch_bounds__(NT) void median5x5_shear_kernel(
    const float* __restrict__ in, float* __restrict__ out) {
    __shared__ float raw[SH][SW];
    __shared__ __align__(16) float scol[OH][5][SW];

    const int bx = blockIdx.x * OW;
    const int by = blockIdx.y * OH;
    const int plane = blockIdx.z;
    const float* src = in + (size_t)plane * (H * W);

    const int tid = threadIdx.x;

    // Phase A: halo load with reflect padding
    for (int k = tid; k < SW * SH; k += NT) {
        int sy = k / SW;
        int sx = k - sy * SW;
        int gy = reflect_idx(by + sy - 2);
        int gx = reflect_idx(bx + sx - 2);
        raw[sy][sx] = src[gy * W + gx];
    }
    __syncthreads();

    // Phase B: sort every 5-high column segment, one per (oy, x)
    for (int k = tid; k < SW * OH; k += NT) {
        int oy = k / SW;
        int x  = k - oy * SW;
        float v0 = raw[oy + 0][x], v1 = raw[oy + 1][x], v2 = raw[oy + 2][x],
              v3 = raw[oy + 3][x], v4 = raw[oy + 4][x];
        sort5(v0, v1, v2, v3, v4);
        scol[oy][0][x] = v0; scol[oy][1][x] = v1; scol[oy][2][x] = v2;
        scol[oy][3][x] = v3; scol[oy][4][x] = v4;
    }
    __syncthreads();

    // Phase C: each thread computes 2 adjacent pixels
    const int oy = tid >> 5;
    const int xp = tid & 31;
    const int x  = 2 * xp;

    float v[5][6];
#pragma unroll
    for (int r = 0; r < 5; r++) {
        const float* row = &scol[oy][r][x];    // 8B-aligned: (oy*5+r)*68 + x is even
        float2 q0 = *(const float2*)(row);
        float2 q1 = *(const float2*)(row + 2);
        float2 q2 = *(const float2*)(row + 4);
        v[r][0] = q0.x; v[r][1] = q0.y; v[r][2] = q1.x;
        v[r][3] = q1.y; v[r][4] = q2.x; v[r][5] = q2.y;
    }

    float med0, med1;
    {
        float A, B, C, D, E, F, G, Hh, I, J, K, L, M;
        top2(v[0][0], v[0][1], v[0][2], v[0][3], v[0][4], A, B);
        top3(v[1][0], v[1][1], v[1][2], v[1][3], v[1][4], C, D, E);
        mid3(v[2][0], v[2][1], v[2][2], v[2][3], v[2][4], F, G, Hh);
        bot3(v[3][0], v[3][1], v[3][2], v[3][3], v[3][4], I, J, K);
        bot2(v[4][0], v[4][1], v[4][2], v[4][3], v[4][4], L, M);
        med0 = sel13(A, B, C, D, E, F, G, Hh, I, J, K, L, M);
    }
    {
        float A, B, C, D, E, F, G, Hh, I, J, K, L, M;
        top2(v[0][1], v[0][2], v[0][3], v[0][4], v[0][5], A, B);
        top3(v[1][1], v[1][2], v[1][3], v[1][4], v[1][5], C, D, E);
        mid3(v[2][1], v[2][2], v[2][3], v[2][4], v[2][5], F, G, Hh);
        bot3(v[3][1], v[3][2], v[3][3], v[3][4], v[3][5], I, J, K);
        bot2(v[4][1], v[4][2], v[4][3], v[4][4], v[4][5], L, M);
        med1 = sel13(A, B, C, D, E, F, G, Hh, I, J, K, L, M);
    }

    float2 o; o.x = med0; o.y = med1;
    *(float2*)(out + (size_t)plane * (H * W) + (by + oy) * W + (bx + x)) = o;
}

extern "C" void kernel_launch(void* const* d_in, const int* in_sizes, int n_in,
                              void* d_out, int out_size) {
    const float* img = (const float*)d_in[0];
    float* out = (float*)d_out;
    int planes = in_sizes[0] / (H * W);   // 4 * 3 = 12

    dim3 block(NT);
    dim3 grid(W / OW, H / OH, planes);
    median5x5_shear_kernel<<<grid, block>>>(img, out);
}

// round 5
// speedup vs baseline: 2.1169x; 1.1323x over previous
#include <cuda_runtime.h>

#define H 512
#define W 512
#define OW 64
#define OH 8
#define SW (OW + 4)   // 68
#define SH (OH + 4)   // 12
#define NT 256

#define CE(a, b) { float _t = fminf(a, b); (b) = fmaxf(a, b); (a) = _t; }

__device__ __forceinline__ int reflect_idx(int i) {
    i = abs(i);                              // -1 -> 1, -2 -> 2
    return (i >= H) ? (2 * H - 2 - i) : i;   // 512 -> 510, 513 -> 509
}

// optimal 5-sort, 9 CE
__device__ __forceinline__ void sort5(float& x0, float& x1, float& x2, float& x3, float& x4) {
    CE(x0, x1); CE(x3, x4); CE(x2, x4); CE(x2, x3); CE(x0, x3);
    CE(x0, x2); CE(x1, x4); CE(x1, x3); CE(x1, x2);
}

// median (7th smallest) of the 13 staircase candidates (validated round 4).
// Chains: A<=B<=E, C<=D<=Hh, F<=G<=K, I<=J<=M, singleton L.
__device__ __forceinline__ float sel13(float A, float B, float C, float D, float E,
                                       float F, float G, float Hh, float I, float J,
                                       float K, float L, float M) {
    CE(A, C); CE(E, Hh); CE(C, E); CE(B, D); CE(B, C); CE(D, E);   // P = A..E,Hh sorted
    CE(F, I); CE(K, M); CE(I, K); CE(G, J); CE(G, I); CE(J, K);    // Q = F..K,M sorted
    float s5 = fmaxf(fmaxf(fmaxf(fminf(A, M), fminf(B, K)),
                           fmaxf(fminf(C, J), fminf(D, I))),
                     fmaxf(fminf(E, G), fminf(Hh, F)));
    float s6 = fmaxf(fmaxf(fmaxf(A, fminf(B, M)),
                           fmaxf(fminf(C, K), fminf(D, J))),
                     fmaxf(fmaxf(fminf(E, I), fminf(Hh, G)), F));
    return fminf(fmaxf(s5, L), s6);
}

__global__ __launch_bounds__(NT, 6) void median5x5_shear2_kernel(
    const float* __restrict__ in, float* __restrict__ out) {
    __shared__ float raw[SH][SW];
    __shared__ __align__(16) float scol[OH][5][SW];

    const int bx = blockIdx.x * OW;
    const int by = blockIdx.y * OH;
    const int plane = blockIdx.z;
    const float* src = in + (size_t)plane * (H * W);

    const int tid = threadIdx.x;

    // Phase A: halo load with reflect padding
    for (int k = tid; k < SW * SH; k += NT) {
        int sy = k / SW;
        int sx = k - sy * SW;
        int gy = reflect_idx(by + sy - 2);
        int gx = reflect_idx(bx + sx - 2);
        raw[sy][sx] = src[gy * W + gx];
    }
    __syncthreads();

    // Phase B: sort every 5-high column segment
    for (int k = tid; k < SW * OH; k += NT) {
        int oy = k / SW;
        int x  = k - oy * SW;
        float v0 = raw[oy + 0][x], v1 = raw[oy + 1][x], v2 = raw[oy + 2][x],
              v3 = raw[oy + 3][x], v4 = raw[oy + 4][x];
        sort5(v0, v1, v2, v3, v4);
        scol[oy][0][x] = v0; scol[oy][1][x] = v1; scol[oy][2][x] = v2;
        scol[oy][3][x] = v3; scol[oy][4][x] = v4;
    }
    __syncthreads();

    // Phase C: 2 adjacent pixels per thread; middle-4 row stats shared
    const int oy = tid >> 5;
    const int x  = (tid & 31) * 2;

#define LOADROW(r, c0, c1, c2, c3, c4, c5)                       \
    float c0, c1, c2, c3, c4, c5;                                \
    {   const float* _p = &scol[oy][r][x];                       \
        float2 _q0 = *(const float2*)(_p);                       \
        float2 _q1 = *(const float2*)(_p + 2);                   \
        float2 _q2 = *(const float2*)(_p + 4);                   \
        c0 = _q0.x; c1 = _q0.y; c2 = _q1.x;                      \
        c3 = _q1.y; c4 = _q2.x; c5 = _q2.y; }

    float A0, B0, A1, B1;
    {   // row 0 (column minima): top2 per window
        LOADROW(0, c0, c1, c2, c3, c4, c5);
        float a = fminf(c1, c2), b = fmaxf(c1, c2);
        float c = fminf(c3, c4), d = fmaxf(c3, c4);
        float B4 = fmaxf(b, d);
        float A4 = fmaxf(fminf(b, d), fmaxf(a, c));   // top2 of middle, A4<=B4
        B0 = fmaxf(B4, c0); A0 = fmaxf(A4, fminf(B4, c0));
        B1 = fmaxf(B4, c5); A1 = fmaxf(A4, fminf(B4, c5));
    }
    float C0, D0, E0, C1, D1, E1;
    {   // row 1: top3 sorted per window
        LOADROW(1, c0, c1, c2, c3, c4, c5);
        float a = fminf(c1, c2), b = fmaxf(c1, c2);
        float c = fminf(c3, c4), d = fmaxf(c3, c4);
        float g = fmaxf(b, d), f = fminf(b, d), e = fmaxf(a, c);
        float p = fminf(e, f), q = fmaxf(e, f);       // middle top3: p<=q<=g
        {   float Ew = fmaxf(g, c0), u = fminf(g, c0);
            float Dw = fmaxf(q, u), v = fminf(q, u);
            C0 = fmaxf(p, v); D0 = Dw; E0 = Ew; }
        {   float Ew = fmaxf(g, c5), u = fminf(g, c5);
            float Dw = fmaxf(q, u), v = fminf(q, u);
            C1 = fmaxf(p, v); D1 = Dw; E1 = Ew; }
    }
    float F0, G0, H0, F1, G1, H1;
    {   // row 2: mid3 per window (positions 1..3 of 5)
        LOADROW(2, c0, s0, s1, s2, s3, c5);
        CE(s0, s1); CE(s2, s3); CE(s0, s2); CE(s1, s3); CE(s1, s2);  // sort4 middle
        F0 = fmaxf(s0, fminf(s1, c0));
        G0 = fmaxf(s1, fminf(s2, c0));
        H0 = fmaxf(s2, fminf(s3, c0));
        F1 = fmaxf(s0, fminf(s1, c5));
        G1 = fmaxf(s1, fminf(s2, c5));
        H1 = fmaxf(s2, fminf(s3, c5));
    }
    float I0, J0, K0, I1, J1, K1;
    {   // row 3: bot3 sorted per window
        LOADROW(3, c0, c1, c2, c3, c4, c5);
        float a = fminf(c1, c2), b = fmaxf(c1, c2);
        float c = fminf(c3, c4), d = fmaxf(c3, c4);
        float m = fminf(a, c), e = fmaxf(a, c), f = fminf(b, d);
        float p = fminf(e, f), q = fmaxf(e, f);       // middle bot3: m<=p<=q
        {   float Iw = fminf(m, c0), u = fmaxf(m, c0);
            float Jw = fminf(p, u), v = fmaxf(p, u);
            I0 = Iw; J0 = Jw; K0 = fminf(q, v); }
        {   float Iw = fminf(m, c5), u = fmaxf(m, c5);
            float Jw = fminf(p, u), v = fmaxf(p, u);
            I1 = Iw; J1 = Jw; K1 = fminf(q, v); }
    }
    float L0, M0, L1, M1;
    {   // row 4 (column maxima): bot2 per window
        LOADROW(4, c0, c1, c2, c3, c4, c5);
        float a = fminf(c1, c2), b = fmaxf(c1, c2);
        float c = fminf(c3, c4), d = fmaxf(c3, c4);
        float Lm = fminf(a, c);
        float Mm = fminf(fmaxf(a, c), fminf(b, d));   // bot2 of middle, Lm<=Mm
        L0 = fminf(Lm, c0); M0 = fminf(Mm, fmaxf(Lm, c0));
        L1 = fminf(Lm, c5); M1 = fminf(Mm, fmaxf(Lm, c5));
    }

    float med0 = sel13(A0, B0, C0, D0, E0, F0, G0, H0, I0, J0, K0, L0, M0);
    float med1 = sel13(A1, B1, C1, D1, E1, F1, G1, H1, I1, J1, K1, L1, M1);

    float2 o; o.x = med0; o.y = med1;
    *(float2*)(out + (size_t)plane * (H * W) + (by + oy) * W + (bx + x)) = o;
#undef LOADROW
}

extern "C" void kernel_launch(void* const* d_in, const int* in_sizes, int n_in,
                              void* d_out, int out_size) {
    const float* img = (const float*)d_in[0];
    float* out = (float*)d_out;
    int planes = in_sizes[0] / (H * W);   // 4 * 3 = 12

    dim3 block(NT);
    dim3 grid(W / OW, H / OH, planes);
    median5x5_shear2_kernel<<<grid, block>>>(img, out);
}

// round 6
// speedup vs baseline: 2.4140x; 1.1404x over previous
#include <cuda_runtime.h>

#define H 512
#define W 512
#define OW 64
#define OH 8
#define SW (OW + 4)   // 68
#define NT 256
#define NSEG (SW * OH)   // 544 column segments

#define CE(a, b) { float _t = fminf(a, b); (b) = fmaxf(a, b); (a) = _t; }

__device__ __forceinline__ int reflect_idx(int i) {
    i = abs(i);                              // -1 -> 1, -2 -> 2
    return (i >= H) ? (2 * H - 2 - i) : i;   // 512 -> 510, 513 -> 509
}

// optimal 5-sort, 9 CE
__device__ __forceinline__ void sort5(float& x0, float& x1, float& x2, float& x3, float& x4) {
    CE(x0, x1); CE(x3, x4); CE(x2, x4); CE(x2, x3); CE(x0, x3);
    CE(x0, x2); CE(x1, x4); CE(x1, x3); CE(x1, x2);
}

// median (7th smallest) of the 13 staircase candidates (validated rounds 4-5).
// Chains: A<=B<=E, C<=D<=Hh, F<=G<=K, I<=J<=M, singleton L.
__device__ __forceinline__ float sel13(float A, float B, float C, float D, float E,
                                       float F, float G, float Hh, float I, float J,
                                       float K, float L, float M) {
    CE(A, C); CE(E, Hh); CE(C, E); CE(B, D); CE(B, C); CE(D, E);   // P sorted
    CE(F, I); CE(K, M); CE(I, K); CE(G, J); CE(G, I); CE(J, K);    // Q sorted
    float s5 = fmaxf(fmaxf(fmaxf(fminf(A, M), fminf(B, K)),
                           fmaxf(fminf(C, J), fminf(D, I))),
                     fmaxf(fminf(E, G), fminf(Hh, F)));
    float s6 = fmaxf(fmaxf(fmaxf(A, fminf(B, M)),
                           fmaxf(fminf(C, K), fminf(D, J))),
                     fmaxf(fmaxf(fminf(E, I), fminf(Hh, G)), F));
    return fminf(fmaxf(s5, L), s6);
}

__global__ __launch_bounds__(NT, 6) void median5x5_shear3_kernel(
    const float* __restrict__ in, float* __restrict__ out) {
    __shared__ __align__(16) float scol[OH][5][SW];

    const int bx = blockIdx.x * OW;
    const int by = blockIdx.y * OH;
    const int plane = blockIdx.z;
    const float* src = in + (size_t)plane * (H * W);

    const int tid = threadIdx.x;

    // block-uniform: does any access leave the image?
    const bool interior = (bx >= 2) & (bx + OW + 2 <= W) & (by >= 2) & (by + OH + 2 <= H);

    // Phase B (fused with load): sort every 5-high column segment straight
    // from global memory into scol.
    if (interior) {
#pragma unroll
        for (int k = tid; k < NSEG; k += NT) {
            int oy = k / SW;
            int x  = k - oy * SW;
            const float* p = src + (by + oy - 2) * W + (bx + x - 2);
            float v0 = p[0], v1 = p[W], v2 = p[2 * W], v3 = p[3 * W], v4 = p[4 * W];
            sort5(v0, v1, v2, v3, v4);
            scol[oy][0][x] = v0; scol[oy][1][x] = v1; scol[oy][2][x] = v2;
            scol[oy][3][x] = v3; scol[oy][4][x] = v4;
        }
    } else {
#pragma unroll
        for (int k = tid; k < NSEG; k += NT) {
            int oy = k / SW;
            int x  = k - oy * SW;
            int gx = reflect_idx(bx + x - 2);
            float v0 = src[reflect_idx(by + oy - 2) * W + gx];
            float v1 = src[reflect_idx(by + oy - 1) * W + gx];
            float v2 = src[reflect_idx(by + oy + 0) * W + gx];
            float v3 = src[reflect_idx(by + oy + 1) * W + gx];
            float v4 = src[reflect_idx(by + oy + 2) * W + gx];
            sort5(v0, v1, v2, v3, v4);
            scol[oy][0][x] = v0; scol[oy][1][x] = v1; scol[oy][2][x] = v2;
            scol[oy][3][x] = v3; scol[oy][4][x] = v4;
        }
    }
    __syncthreads();

    // Phase C: 2 adjacent pixels per thread; middle-4 row stats shared
    const int oy = tid >> 5;
    const int x  = (tid & 31) * 2;

#define LOADROW(r, c0, c1, c2, c3, c4, c5)                       \
    float c0, c1, c2, c3, c4, c5;                                \
    {   const float* _p = &scol[oy][r][x];                       \
        float2 _q0 = *(const float2*)(_p);                       \
        float2 _q1 = *(const float2*)(_p + 2);                   \
        float2 _q2 = *(const float2*)(_p + 4);                   \
        c0 = _q0.x; c1 = _q0.y; c2 = _q1.x;                      \
        c3 = _q1.y; c4 = _q2.x; c5 = _q2.y; }

    float A0, B0, A1, B1;
    {   // row 0 (column minima): top2 per window
        LOADROW(0, c0, c1, c2, c3, c4, c5);
        float a = fminf(c1, c2), b = fmaxf(c1, c2);
        float c = fminf(c3, c4), d = fmaxf(c3, c4);
        float B4 = fmaxf(b, d);
        float A4 = fmaxf(fminf(b, d), fmaxf(a, c));   // top2 of middle, A4<=B4
        B0 = fmaxf(B4, c0); A0 = fmaxf(A4, fminf(B4, c0));
        B1 = fmaxf(B4, c5); A1 = fmaxf(A4, fminf(B4, c5));
    }
    float C0, D0, E0, C1, D1, E1;
    {   // row 1: top3 sorted per window
        LOADROW(1, c0, c1, c2, c3, c4, c5);
        float a = fminf(c1, c2), b = fmaxf(c1, c2);
        float c = fminf(c3, c4), d = fmaxf(c3, c4);
        float g = fmaxf(b, d), f = fminf(b, d), e = fmaxf(a, c);
        float p = fminf(e, f), q = fmaxf(e, f);       // middle top3: p<=q<=g
        {   float Ew = fmaxf(g, c0), u = fminf(g, c0);
            float Dw = fmaxf(q, u), v = fminf(q, u);
            C0 = fmaxf(p, v); D0 = Dw; E0 = Ew; }
        {   float Ew = fmaxf(g, c5), u = fminf(g, c5);
            float Dw = fmaxf(q, u), v = fminf(q, u);
            C1 = fmaxf(p, v); D1 = Dw; E1 = Ew; }
    }
    float F0, G0, H0, F1, G1, H1;
    {   // row 2: mid3 per window (positions 1..3 of 5)
        LOADROW(2, c0, s0, s1, s2, s3, c5);
        CE(s0, s1); CE(s2, s3); CE(s0, s2); CE(s1, s3); CE(s1, s2);  // sort4 middle
        F0 = fmaxf(s0, fminf(s1, c0));
        G0 = fmaxf(s1, fminf(s2, c0));
        H0 = fmaxf(s2, fminf(s3, c0));
        F1 = fmaxf(s0, fminf(s1, c5));
        G1 = fmaxf(s1, fminf(s2, c5));
        H1 = fmaxf(s2, fminf(s3, c5));
    }
    float I0, J0, K0, I1, J1, K1;
    {   // row 3: bot3 sorted per window
        LOADROW(3, c0, c1, c2, c3, c4, c5);
        float a = fminf(c1, c2), b = fmaxf(c1, c2);
        float c = fminf(c3, c4), d = fmaxf(c3, c4);
        float m = fminf(a, c), e = fmaxf(a, c), f = fminf(b, d);
        float p = fminf(e, f), q = fmaxf(e, f);       // middle bot3: m<=p<=q
        {   float Iw = fminf(m, c0), u = fmaxf(m, c0);
            float Jw = fminf(p, u), v = fmaxf(p, u);
            I0 = Iw; J0 = Jw; K0 = fminf(q, v); }
        {   float Iw = fminf(m, c5), u = fmaxf(m, c5);
            float Jw = fminf(p, u), v = fmaxf(p, u);
            I1 = Iw; J1 = Jw; K1 = fminf(q, v); }
    }
    float L0, M0, L1, M1;
    {   // row 4 (column maxima): bot2 per window
        LOADROW(4, c0, c1, c2, c3, c4, c5);
        float a = fminf(c1, c2), b = fmaxf(c1, c2);
        float c = fminf(c3, c4), d = fmaxf(c3, c4);
        float Lm = fminf(a, c);
        float Mm = fminf(fmaxf(a, c), fminf(b, d));   // bot2 of middle, Lm<=Mm
        L0 = fminf(Lm, c0); M0 = fminf(Mm, fmaxf(Lm, c0));
        L1 = fminf(Lm, c5); M1 = fminf(Mm, fmaxf(Lm, c5));
    }

    float med0 = sel13(A0, B0, C0, D0, E0, F0, G0, H0, I0, J0, K0, L0, M0);
    float med1 = sel13(A1, B1, C1, D1, E1, F1, G1, H1, I1, J1, K1, L1, M1);

    float2 o; o.x = med0; o.y = med1;
    *(float2*)(out + (size_t)plane * (H * W) + (by + oy) * W + (bx + x)) = o;
#undef LOADROW
}

extern "C" void kernel_launch(void* const* d_in, const int* in_sizes, int n_in,
                              void* d_out, int out_size) {
    const float* img = (const float*)d_in[0];
    float* out = (float*)d_out;
    int planes = in_sizes[0] / (H * W);   // 4 * 3 = 12

    dim3 block(NT);
    dim3 grid(W / OW, H / OH, planes);
    median5x5_shear3_kernel<<<grid, block>>>(img, out);
}

// round 7
// speedup vs baseline: 3.1511x; 1.3053x over previous
#include <cuda_runtime.h>
#include <cuda_fp16.h>

#define H 512
#define W 512
#define OW 64
#define OH 8
#define NPK 34            // even packs per row: cover halo cols 0..67
#define NT 256

#define CEH(a, b) { __half2 _t = __hmin2(a, b); (b) = __hmax2(a, b); (a) = _t; }

__device__ __forceinline__ int reflect_idx(int i) {
    i = abs(i);
    return (i >= H) ? (2 * H - 2 - i) : i;
}

// optimal 5-sort, 9 CE (elementwise on half2 lanes)
__device__ __forceinline__ void sort5h(__half2& x0, __half2& x1, __half2& x2,
                                       __half2& x3, __half2& x4) {
    CEH(x0, x1); CEH(x3, x4); CEH(x2, x4); CEH(x2, x3); CEH(x0, x3);
    CEH(x0, x2); CEH(x1, x4); CEH(x1, x3); CEH(x1, x2);
}

// median (7th smallest) of the 13 staircase candidates, packed.
// Chains: A<=B<=E, C<=D<=Hh, F<=G<=K, I<=J<=M, singleton L. (validated R4-R6)
__device__ __forceinline__ __half2 sel13h(__half2 A, __half2 B, __half2 C, __half2 D,
                                          __half2 E, __half2 F, __half2 G, __half2 Hh,
                                          __half2 I, __half2 J, __half2 K, __half2 L,
                                          __half2 M) {
    CEH(A, C); CEH(E, Hh); CEH(C, E); CEH(B, D); CEH(B, C); CEH(D, E);   // P sorted
    CEH(F, I); CEH(K, M); CEH(I, K); CEH(G, J); CEH(G, I); CEH(J, K);    // Q sorted
    __half2 s5 = __hmax2(__hmax2(__hmax2(__hmin2(A, M), __hmin2(B, K)),
                                 __hmax2(__hmin2(C, J), __hmin2(D, I))),
                         __hmax2(__hmin2(E, G), __hmin2(Hh, F)));
    __half2 s6 = __hmax2(__hmax2(__hmax2(A, __hmin2(B, M)),
                                 __hmax2(__hmin2(C, K), __hmin2(D, J))),
                         __hmax2(__hmax2(__hmin2(E, I), __hmin2(Hh, G)), F));
    return __hmin2(__hmax2(s5, L), s6);
}

__device__ __forceinline__ __half2 u2h(unsigned u) {
    return *reinterpret_cast<__half2*>(&u);
}
__device__ __forceinline__ unsigned h2u(__half2 h) {
    return *reinterpret_cast<unsigned*>(&h);
}

__global__ __launch_bounds__(NT, 6) void median5x5_h2_kernel(
    const float* __restrict__ in, float* __restrict__ out) {
    // sorted even column-packs: pack p holds halo columns (2p, 2p+1) as half2
    __shared__ unsigned scolp[OH][5][NPK];

    const int bx = blockIdx.x * OW;
    const int by = blockIdx.y * OH;
    const int plane = blockIdx.z;
    const float* src = in + (size_t)plane * (H * W);

    const int tid = threadIdx.x;
    const bool interior = (bx >= 2) & (bx + OW + 2 <= W) & (by >= 2) & (by + OH + 2 <= H);

    // Phase B: sort each even column-pack of 5 vertically-adjacent rows.
    // 34 packs x 8 oy = 272 items.
    for (int k = tid; k < NPK * OH; k += NT) {
        int oy = k / NPK;
        int sp = (k - oy * NPK) * 2;           // even halo column
        __half2 v0, v1, v2, v3, v4;
        if (interior) {
            const float* p = src + (by + oy - 2) * W + (bx + sp - 2);   // 8B aligned
            v0 = __float22half2_rn(*(const float2*)(p));
            v1 = __float22half2_rn(*(const float2*)(p + W));
            v2 = __float22half2_rn(*(const float2*)(p + 2 * W));
            v3 = __float22half2_rn(*(const float2*)(p + 3 * W));
            v4 = __float22half2_rn(*(const float2*)(p + 4 * W));
        } else {
            int gx0 = reflect_idx(bx + sp - 2);
            int gx1 = reflect_idx(bx + sp - 1);
            int g0 = reflect_idx(by + oy - 2) * W;
            int g1 = reflect_idx(by + oy - 1) * W;
            int g2 = reflect_idx(by + oy + 0) * W;
            int g3 = reflect_idx(by + oy + 1) * W;
            int g4 = reflect_idx(by + oy + 2) * W;
            v0 = __floats2half2_rn(src[g0 + gx0], src[g0 + gx1]);
            v1 = __floats2half2_rn(src[g1 + gx0], src[g1 + gx1]);
            v2 = __floats2half2_rn(src[g2 + gx0], src[g2 + gx1]);
            v3 = __floats2half2_rn(src[g3 + gx0], src[g3 + gx1]);
            v4 = __floats2half2_rn(src[g4 + gx0], src[g4 + gx1]);
        }
        sort5h(v0, v1, v2, v3, v4);
        scolp[oy][0][k - oy * NPK] = h2u(v0);
        scolp[oy][1][k - oy * NPK] = h2u(v1);
        scolp[oy][2][k - oy * NPK] = h2u(v2);
        scolp[oy][3][k - oy * NPK] = h2u(v3);
        scolp[oy][4][k - oy * NPK] = h2u(v4);
    }
    __syncthreads();

    // Phase C: 2 adjacent pixels per thread, packed in half2 lanes.
    // Window packs for row r: positions 2xp+j (j=0..4); odd packs via PRMT.
    const int oy = tid >> 5;
    const int xp = tid & 31;

    __half2 A, B, C, D, E, F, G, Hh, I, J, K, L, M;

    {   // row 0 (column minima): top2 -> A<=B
        unsigned e0 = scolp[oy][0][xp], e1 = scolp[oy][0][xp + 1], e2 = scolp[oy][0][xp + 2];
        __half2 w0 = u2h(e0), w2 = u2h(e1), w4 = u2h(e2);
        __half2 w1 = u2h(__byte_perm(e0, e1, 0x5432));
        __half2 w3 = u2h(__byte_perm(e1, e2, 0x5432));
        __half2 a = __hmin2(w0, w1), b = __hmax2(w0, w1);
        __half2 c = __hmin2(w2, w3), d = __hmax2(w2, w3);
        __half2 e = __hmax2(a, c);
        __half2 f = __hmin2(b, d), g = __hmax2(b, d);
        B = __hmax2(g, w4);
        __half2 h = __hmin2(g, w4);
        A = __hmax2(__hmax2(f, e), h);
    }
    {   // row 1: top3 -> C<=D<=E
        unsigned e0 = scolp[oy][1][xp], e1 = scolp[oy][1][xp + 1], e2 = scolp[oy][1][xp + 2];
        __half2 w0 = u2h(e0), w2 = u2h(e1), w4 = u2h(e2);
        __half2 w1 = u2h(__byte_perm(e0, e1, 0x5432));
        __half2 w3 = u2h(__byte_perm(e1, e2, 0x5432));
        __half2 a = __hmin2(w0, w1), b = __hmax2(w0, w1);
        __half2 c = __hmin2(w2, w3), d = __hmax2(w2, w3);
        __half2 e = __hmax2(a, c);
        __half2 f = __hmin2(b, d), g = __hmax2(b, d);
        __half2 p = __hmin2(e, f), q = __hmax2(e, f);
        E = __hmax2(g, w4);
        __half2 u = __hmin2(g, w4);
        D = __hmax2(q, u);
        __half2 v = __hmin2(q, u);
        C = __hmax2(p, v);
    }
    {   // row 2: mid3 -> F<=G<=Hh
        unsigned e0 = scolp[oy][2][xp], e1 = scolp[oy][2][xp + 1], e2 = scolp[oy][2][xp + 2];
        __half2 x0 = u2h(e0), x2 = u2h(e1), x4 = u2h(e2);
        __half2 x1 = u2h(__byte_perm(e0, e1, 0x5432));
        __half2 x3 = u2h(__byte_perm(e1, e2, 0x5432));
        CEH(x0, x1); CEH(x2, x3); CEH(x0, x2);
        x4 = __hmax2(x0, x4);            // drop lane min
        CEH(x1, x4);
        x3 = __hmin2(x3, x4);            // drop lane max
        CEH(x1, x2); CEH(x2, x3); CEH(x1, x2);
        F = x1; G = x2; Hh = x3;
    }
    {   // row 3: bot3 -> I<=J<=K
        unsigned e0 = scolp[oy][3][xp], e1 = scolp[oy][3][xp + 1], e2 = scolp[oy][3][xp + 2];
        __half2 w0 = u2h(e0), w2 = u2h(e1), w4 = u2h(e2);
        __half2 w1 = u2h(__byte_perm(e0, e1, 0x5432));
        __half2 w3 = u2h(__byte_perm(e1, e2, 0x5432));
        __half2 a = __hmin2(w0, w1), b = __hmax2(w0, w1);
        __half2 c = __hmin2(w2, w3), d = __hmax2(w2, w3);
        __half2 e = __hmin2(b, d);
        __half2 f = __hmin2(a, c), g = __hmax2(a, c);
        __half2 p = __hmin2(g, e), q = __hmax2(g, e);
        I = __hmin2(f, w4);
        __half2 u = __hmax2(f, w4);
        J = __hmin2(p, u);
        __half2 v = __hmax2(p, u);
        K = __hmin2(q, v);
    }
    {   // row 4 (column maxima): bot2 -> L<=M
        unsigned e0 = scolp[oy][4][xp], e1 = scolp[oy][4][xp + 1], e2 = scolp[oy][4][xp + 2];
        __half2 w0 = u2h(e0), w2 = u2h(e1), w4 = u2h(e2);
        __half2 w1 = u2h(__byte_perm(e0, e1, 0x5432));
        __half2 w3 = u2h(__byte_perm(e1, e2, 0x5432));
        __half2 a = __hmin2(w0, w1), b = __hmax2(w0, w1);
        __half2 c = __hmin2(w2, w3), d = __hmax2(w2, w3);
        __half2 e = __hmin2(b, d);
        __half2 f = __hmin2(a, c), g = __hmax2(a, c);
        L = __hmin2(f, w4);
        __half2 h = __hmax2(f, w4);
        M = __hmin2(__hmin2(g, e), h);
    }

    __half2 med = sel13h(A, B, C, D, E, F, G, Hh, I, J, K, L, M);

    float2 o;
    o.x = __low2float(med);
    o.y = __high2float(med);
    *(float2*)(out + (size_t)plane * (H * W) + (by + oy) * W + (bx + 2 * xp)) = o;
}

extern "C" void kernel_launch(void* const* d_in, const int* in_sizes, int n_in,
                              void* d_out, int out_size) {
    const float* img = (const float*)d_in[0];
    float* out = (float*)d_out;
    int planes = in_sizes[0] / (H * W);   // 4 * 3 = 12

    dim3 block(NT);
    dim3 grid(W / OW, H / OH, planes);
    median5x5_h2_kernel<<<grid, block>>>(img, out);
}